// round 11
// baseline (speedup 1.0000x reference)
#include <cuda_runtime.h>
#include <cuda_bf16.h>
#include <cstdint>

#define T_STEPS 512
#define NBATCH  64
#define IDIM    512
#define HDIM    512
#define G4H     2048
#define NBLOCKS 128

// ---------------- device scratch (allocation-free rule) ----------------
__device__ float         g_xp[(size_t)T_STEPS * NBATCH * G4H];  // [T*B, 4H]
__device__ __nv_bfloat16 g_hh[2][NBATCH * HDIM];                // ping-pong h hi [b][k]
__device__ __nv_bfloat16 g_hl[2][NBATCH * HDIM];                // ping-pong h lo [b][k]
__device__ unsigned      g_flags[NBLOCKS];                      // per-block step counters
__device__ unsigned      g_count;
__device__ unsigned      g_gen;
__device__ __nv_bfloat16 g_Ahi[(size_t)T_STEPS * NBATCH * IDIM];
__device__ __nv_bfloat16 g_Alo[(size_t)T_STEPS * NBATCH * IDIM];
__device__ __nv_bfloat16 g_Bhi[(size_t)G4H * IDIM];
__device__ __nv_bfloat16 g_Blo[(size_t)G4H * IDIM];

// ---------------- portable PTX helpers (valid on plain sm_103) ----------------
__device__ __forceinline__ uint32_t smem_u32(const void* p) {
    uint32_t a;
    asm("{ .reg .u64 t; cvta.to.shared.u64 t, %1; cvt.u32.u64 %0, t; }" : "=r"(a) : "l"(p));
    return a;
}
#define CP_ASYNC16(dst, src) \
    asm volatile("cp.async.cg.shared.global [%0], [%1], 16;" :: "r"(dst), "l"(src))
#define CP_COMMIT() asm volatile("cp.async.commit_group;" ::: "memory")
#define CP_WAIT(n)  asm volatile("cp.async.wait_group %0;" :: "n"(n) : "memory")
#define LDSM_X4(r0, r1, r2, r3, addr)                                        \
    asm volatile("ldmatrix.sync.aligned.m8n8.x4.shared.b16 {%0,%1,%2,%3}, [%4];" \
                 : "=r"(r0), "=r"(r1), "=r"(r2), "=r"(r3) : "r"(addr))
#define MMA_BF16(c, a, b)                                                    \
    asm volatile("mma.sync.aligned.m16n8k16.row.col.f32.bf16.bf16.f32 "      \
                 "{%0,%1,%2,%3},{%4,%5,%6,%7},{%8,%9},{%0,%1,%2,%3};"        \
                 : "+f"((c)[0]), "+f"((c)[1]), "+f"((c)[2]), "+f"((c)[3])    \
                 : "r"((a)[0]), "r"((a)[1]), "r"((a)[2]), "r"((a)[3]),       \
                   "r"((b)[0]), "r"((b)[1]))
__device__ __forceinline__ unsigned ld_acq(const unsigned* p) {
    unsigned v;
    asm volatile("ld.acquire.gpu.global.b32 %0, [%1];" : "=r"(v) : "l"(p) : "memory");
    return v;
}
__device__ __forceinline__ void st_rel(unsigned* p, unsigned v) {
    asm volatile("st.release.gpu.global.b32 [%0], %1;" :: "l"(p), "r"(v) : "memory");
}

// ---------------------------------------------------------------------------
// Split fp32 -> (hi, lo) bf16 pair
// ---------------------------------------------------------------------------
__global__ void split_bf16(const float* __restrict__ src, __nv_bfloat16* __restrict__ hi,
                           __nv_bfloat16* __restrict__ lo, int n) {
    int i = blockIdx.x * blockDim.x + threadIdx.x;
    if (i < n) {
        float v = src[i];
        __nv_bfloat16 h = __float2bfloat16(v);
        hi[i] = h;
        lo[i] = __float2bfloat16(v - __bfloat162float(h));
    }
}

// ---------------------------------------------------------------------------
// HMMA split-bf16 GEMM: g_xp[M=32768, N=2048] = A @ B^T + bias  (unchanged, proven)
// ---------------------------------------------------------------------------
#define XSTG 40960
#define TROW 80

__device__ __forceinline__ void xp_load_stage(uint32_t smb, int stage, int kc,
                                              int my, int nx, int tid) {
    const uint32_t sb = smb + stage * XSTG;
#pragma unroll
    for (int t = 0; t < 8; t++) {
        int i = tid + t * 256;
        int tile = i >> 9;
        int idx  = i & 511;
        int row  = idx >> 2;
        int q    = idx & 3;
        const __nv_bfloat16* src;
        int grow;
        if (tile == 0)      { src = g_Ahi; grow = my * 128 + row; }
        else if (tile == 1) { src = g_Alo; grow = my * 128 + row; }
        else if (tile == 2) { src = g_Bhi; grow = nx * 128 + row; }
        else                { src = g_Blo; grow = nx * 128 + row; }
        uint32_t dst = sb + tile * 10240 + row * TROW + q * 16;
        CP_ASYNC16(dst, src + (size_t)grow * IDIM + kc * 32 + q * 8);
    }
}

__global__ __launch_bounds__(256, 1)
void xproj_hmma(const float* __restrict__ bih, const float* __restrict__ bhh) {
    extern __shared__ char sm[];
    const uint32_t smb = smem_u32(sm);
    const int tid  = threadIdx.x;
    const int lane = tid & 31;
    const int wid  = tid >> 5;
    const int nx = blockIdx.x, my = blockIdx.y;
    const int warp_m = wid & 3, warp_n = wid >> 2;
    const int m_base = warp_m * 32, n_base = warp_n * 64;
    float* b_sh = (float*)(sm + 81920);

    if (tid < 128) b_sh[tid] = bih[nx * 128 + tid] + bhh[nx * 128 + tid];

    const uint32_t a_off = (uint32_t)(m_base + (lane & 15)) * TROW + (lane >> 4) * 16;
    const uint32_t b_off = (uint32_t)(n_base + (lane & 7) + ((lane >> 4) & 1) * 8) * TROW
                         + ((lane >> 3) & 1) * 16;

    float acc[2][8][4];
#pragma unroll
    for (int am = 0; am < 2; am++)
#pragma unroll
        for (int an = 0; an < 8; an++)
#pragma unroll
            for (int j = 0; j < 4; j++) acc[am][an][j] = 0.f;

    xp_load_stage(smb, 0, 0, my, nx, tid);
    CP_COMMIT();

    for (int c = 0; c < 16; c++) {
        if (c + 1 < 16) {
            xp_load_stage(smb, (c + 1) & 1, c + 1, my, nx, tid);
            CP_COMMIT();
            CP_WAIT(1);
        } else {
            CP_WAIT(0);
        }
        __syncthreads();

        const uint32_t sb = smb + (c & 1) * XSTG;
        const uint32_t aHi = sb + a_off;
        const uint32_t aLo = aHi + 10240;
        const uint32_t bHi = sb + 20480 + b_off;
        const uint32_t bLo = bHi + 10240;
#pragma unroll
        for (int ks = 0; ks < 2; ks++) {
            uint32_t ah[2][4], al[2][4], bh[8][2], bl[8][2];
            LDSM_X4(ah[0][0], ah[0][1], ah[0][2], ah[0][3], aHi + ks * 32);
            LDSM_X4(ah[1][0], ah[1][1], ah[1][2], ah[1][3], aHi + 1280 + ks * 32);
            LDSM_X4(al[0][0], al[0][1], al[0][2], al[0][3], aLo + ks * 32);
            LDSM_X4(al[1][0], al[1][1], al[1][2], al[1][3], aLo + 1280 + ks * 32);
#pragma unroll
            for (int p = 0; p < 4; p++) {
                LDSM_X4(bh[2*p][0], bh[2*p][1], bh[2*p+1][0], bh[2*p+1][1],
                        bHi + p * 1280 + ks * 32);
                LDSM_X4(bl[2*p][0], bl[2*p][1], bl[2*p+1][0], bl[2*p+1][1],
                        bLo + p * 1280 + ks * 32);
            }
#pragma unroll
            for (int am = 0; am < 2; am++)
#pragma unroll
                for (int an = 0; an < 8; an++) {
                    MMA_BF16(acc[am][an], ah[am], bh[an]);
                    MMA_BF16(acc[am][an], ah[am], bl[an]);
                    MMA_BF16(acc[am][an], al[am], bh[an]);
                }
        }
        __syncthreads();
    }

    const int qr = lane >> 2, qc = (lane & 3) * 2;
#pragma unroll
    for (int am = 0; am < 2; am++) {
        const size_t r0 = (size_t)my * 128 + m_base + am * 16 + qr;
#pragma unroll
        for (int an = 0; an < 8; an++) {
            const int cb = n_base + an * 8 + qc;
            const float b0 = b_sh[cb], b1 = b_sh[cb + 1];
            const size_t col = (size_t)nx * 128 + cb;
            *(float2*)&g_xp[r0 * G4H + col] =
                make_float2(acc[am][an][0] + b0, acc[am][an][1] + b1);
            *(float2*)&g_xp[(r0 + 8) * G4H + col] =
                make_float2(acc[am][an][2] + b0, acc[am][an][3] + b1);
        }
    }
}

// ---------------------------------------------------------------------------
// Atomic grid barrier — used ONCE at init (also resets flag state per replay)
// ---------------------------------------------------------------------------
__device__ __forceinline__ void grid_barrier() {
    __threadfence();
    __syncthreads();
    if (threadIdx.x == 0) {
        volatile unsigned* vgen = &g_gen;
        unsigned gen = *vgen;
        if (atomicAdd(&g_count, 1u) == NBLOCKS - 1u) {
            g_count = 0u;
            __threadfence();
            atomicAdd(&g_gen, 1u);
        } else {
            while (*vgen == gen) { __nanosleep(64); }
        }
    }
    __syncthreads();
}

// ---------------------------------------------------------------------------
// Persistent recurrence, tensor-core edition.
// 128 blocks = 64 col-groups (8 cols) x 2 batch-groups (32 batches).
// Per step per block: gates[32b, 32r] = h[32b,512] @ Whh_sub[32r,512]^T, via
// split-bf16 HMMA (hi*hi + hi*lo + lo*hi), warps = 2m x 2n x 2k.
// SMEM (bytes): h_hi[0,33280) h_lo[33280,66560) w_hi[66560,99840)
//               w_lo[99840,133120) part[133120,141824)   (row pitch 1040B)
// Sync: per-block release-flag array; group (blockIdx.y) independence.
// ---------------------------------------------------------------------------
#define COLS 8
#define BB   32
#define HROWB 1040

__global__ __launch_bounds__(256, 1)
void lstm_rec(const float* __restrict__ Whh, float* __restrict__ out) {
    extern __shared__ char sm[];
    const uint32_t smb = smem_u32(sm);
    __nv_bfloat16* w_hi = (__nv_bfloat16*)(sm + 66560);
    __nv_bfloat16* w_lo = (__nv_bfloat16*)(sm + 99840);
    float* part = (float*)(sm + 133120);

    const int tid  = threadIdx.x;
    const int lane = tid & 31;
    const int wid  = tid >> 5;
    const int colbase = blockIdx.x * COLS;
    const int bbase   = blockIdx.y * BB;
    const int fb      = (blockIdx.y << 6) + blockIdx.x;   // flag index

    // ---- init: split W_hh slice into SMEM (r = gate*8 + col, k-major) ----
    for (int idx = tid; idx < 32 * 512; idx += 256) {
        int r = idx >> 9, k = idx & 511;
        int g = r >> 3, c = r & 7;
        float v = __ldg(&Whh[((size_t)(g * HDIM + colbase + c)) * HDIM + k]);
        __nv_bfloat16 h = __float2bfloat16(v);
        w_hi[r * 520 + k] = h;
        w_lo[r * 520 + k] = __float2bfloat16(v - __bfloat162float(h));
    }
    // zero own slice of h buffer 0 and own flag
    {
        int b = tid >> 3, c = tid & 7;
        g_hh[0][(bbase + b) * HDIM + colbase + c] = __float2bfloat16(0.f);
        g_hl[0][(bbase + b) * HDIM + colbase + c] = __float2bfloat16(0.f);
    }
    if (tid == 0) g_flags[fb] = 0u;
    grid_barrier();

    // warp decomposition: 2m x 2n x 2k
    const int mh = wid & 1, nh = (wid >> 1) & 1, kh = wid >> 2;
    const uint32_t a_off = (uint32_t)(mh * 16 + (lane & 15)) * HROWB
                         + (lane >> 4) * 16 + kh * 512;
    const uint32_t b_off = (uint32_t)(nh * 16 + (lane & 7) + ((lane >> 4) & 1) * 8) * HROWB
                         + ((lane >> 3) & 1) * 16 + kh * 512;
    const uint32_t aHi = smb + a_off;
    const uint32_t aLo = aHi + 33280;
    const uint32_t bHi = smb + 66560 + b_off;
    const uint32_t bLo = bHi + 33280;

    const int qr = lane >> 2, qc = (lane & 3) * 2;
    const int b_ep = tid >> 3;         // epilogue batch 0..31
    const int c_ep = tid & 7;          // epilogue col 0..7
    float creg = 0.f;

    for (int t = 0; t < T_STEPS; t++) {
        const int cur = t & 1;
        // prefetch x_proj gates (independent of h; hides under flag wait)
        float xp[4];
        {
            const float* xpp = g_xp + ((size_t)t * NBATCH + (bbase + b_ep)) * G4H
                               + colbase + c_ep;
#pragma unroll
            for (int g = 0; g < 4; g++) xp[g] = __ldg(xpp + (size_t)g * HDIM);
        }
        // wait for our batch-group's producers to finish step t-1
        if (t > 0 && tid < 64) {
            const unsigned* fp = &g_flags[(blockIdx.y << 6) + tid];
            while (ld_acq(fp) < (unsigned)t) { }
        }
        __syncthreads();

        // stage h slice (32 batches x 512, hi+lo) into SMEM via cp.async (L2 path)
        {
            const __nv_bfloat16* shi = g_hh[cur] + (size_t)bbase * HDIM;
            const __nv_bfloat16* slo = g_hl[cur] + (size_t)bbase * HDIM;
#pragma unroll
            for (int it = 0; it < 16; it++) {
                int i = tid + it * 256;          // 0..4095
                int half = i >> 11;
                int idx  = i & 2047;
                int b    = idx >> 6;
                int k8   = idx & 63;
                const __nv_bfloat16* src = (half ? slo : shi) + (size_t)b * HDIM + k8 * 8;
                CP_ASYNC16(smb + half * 33280 + b * HROWB + k8 * 16, src);
            }
        }
        CP_COMMIT();
        CP_WAIT(0);
        __syncthreads();

        // micro-GEMM: this warp's 16b x 16r tile over its K half (3 products)
        float acc[2][4];
#pragma unroll
        for (int an = 0; an < 2; an++)
#pragma unroll
            for (int j = 0; j < 4; j++) acc[an][j] = 0.f;
#pragma unroll
        for (int ks = 0; ks < 16; ks++) {
            uint32_t ah[4], al[4], bh[2][2], bl[2][2];
            LDSM_X4(ah[0], ah[1], ah[2], ah[3], aHi + ks * 32);
            LDSM_X4(al[0], al[1], al[2], al[3], aLo + ks * 32);
            LDSM_X4(bh[0][0], bh[0][1], bh[1][0], bh[1][1], bHi + ks * 32);
            LDSM_X4(bl[0][0], bl[0][1], bl[1][0], bl[1][1], bLo + ks * 32);
#pragma unroll
            for (int an = 0; an < 2; an++) {
                MMA_BF16(acc[an], ah, bh[an]);
                MMA_BF16(acc[an], ah, bl[an]);
                MMA_BF16(acc[an], al, bh[an]);
            }
        }
        // store K-half partials (pitch 34 floats)
        {
            float* pp = part + kh * 1088;
            const int row0 = mh * 16 + qr;
#pragma unroll
            for (int an = 0; an < 2; an++) {
                const int col = nh * 16 + an * 8 + qc;
                *(float2*)&pp[row0 * 34 + col] = make_float2(acc[an][0], acc[an][1]);
                *(float2*)&pp[(row0 + 8) * 34 + col] = make_float2(acc[an][2], acc[an][3]);
            }
        }
        __syncthreads();

        // epilogue: one (batch,col) per thread
        {
            float s[4];
#pragma unroll
            for (int g = 0; g < 4; g++) {
                int r = g * 8 + c_ep;
                s[g] = part[b_ep * 34 + r] + part[1088 + b_ep * 34 + r] + xp[g];
            }
            float iv = 1.f / (1.f + expf(-s[0]));
            float fv = 1.f / (1.f + expf(-s[1]));
            float gv = tanhf(s[2]);
            float ov = 1.f / (1.f + expf(-s[3]));
            creg = fv * creg + iv * gv;
            float hn = ov * tanhf(creg);
            __nv_bfloat16 hh = __float2bfloat16(hn);
            __nv_bfloat16 hl = __float2bfloat16(hn - __bfloat162float(hh));
            const size_t hidx = (size_t)(bbase + b_ep) * HDIM + colbase + c_ep;
            g_hh[cur ^ 1][hidx] = hh;
            g_hl[cur ^ 1][hidx] = hl;
            out[((size_t)t * NBATCH + bbase + b_ep) * HDIM + colbase + c_ep] = hn;
        }
        // release: our h(t) writes are globally visible before flag = t+1
        __threadfence();
        __syncthreads();
        if (tid == 0) st_rel(&g_flags[fb], (unsigned)(t + 1));
    }
}

// ---------------------------------------------------------------------------
extern "C" void kernel_launch(void* const* d_in, const int* in_sizes, int n_in,
                              void* d_out, int out_size) {
    const float* x   = (const float*)d_in[0];
    const float* Wih = (const float*)d_in[1];
    const float* Whh = (const float*)d_in[2];
    const float* bih = (const float*)d_in[3];
    const float* bhh = (const float*)d_in[4];
    float* out = (float*)d_out;

    cudaFuncSetAttribute((const void*)xproj_hmma,
                         cudaFuncAttributeMaxDynamicSharedMemorySize, 82944);
    cudaFuncSetAttribute((const void*)lstm_rec,
                         cudaFuncAttributeMaxDynamicSharedMemorySize, 141824);

    __nv_bfloat16 *ahi, *alo, *bhi, *blo;
    cudaGetSymbolAddress((void**)&ahi, g_Ahi);
    cudaGetSymbolAddress((void**)&alo, g_Alo);
    cudaGetSymbolAddress((void**)&bhi, g_Bhi);
    cudaGetSymbolAddress((void**)&blo, g_Blo);

    const int nA = T_STEPS * NBATCH * IDIM;   // 16.8M
    const int nB = G4H * IDIM;                // 1M
    split_bf16<<<(nA + 255) / 256, 256>>>(x, ahi, alo, nA);
    split_bf16<<<(nB + 255) / 256, 256>>>(Wih, bhi, blo, nB);

    xproj_hmma<<<dim3(G4H / 128, (T_STEPS * NBATCH) / 128), 256, 82944>>>(bih, bhh);
    lstm_rec<<<dim3(64, 2), 256, 141824>>>(Whh, out);
}

// round 15
// speedup vs baseline: 1.2187x; 1.2187x over previous
#include <cuda_runtime.h>
#include <cuda_bf16.h>
#include <cstdint>

#define T_STEPS 512
#define NBATCH  64
#define IDIM    512
#define HDIM    512
#define G4H     2048
#define NBLOCKS 128

// ---------------- device scratch (allocation-free rule) ----------------
__device__ float         g_xp[(size_t)T_STEPS * NBATCH * G4H];  // [T*B, 4H]
__device__ __nv_bfloat16 g_hh[2][NBATCH * HDIM];                // ping-pong h hi [b][k]
__device__ __nv_bfloat16 g_hl[2][NBATCH * HDIM];                // ping-pong h lo [b][k]
__device__ unsigned      g_flags[NBLOCKS];                      // per-block step counters
__device__ unsigned      g_count;
__device__ unsigned      g_gen;
__device__ __nv_bfloat16 g_Ahi[(size_t)T_STEPS * NBATCH * IDIM];
__device__ __nv_bfloat16 g_Alo[(size_t)T_STEPS * NBATCH * IDIM];
__device__ __nv_bfloat16 g_Bhi[(size_t)G4H * IDIM];
__device__ __nv_bfloat16 g_Blo[(size_t)G4H * IDIM];

// ---------------- portable PTX helpers (valid on plain sm_103) ----------------
__device__ __forceinline__ uint32_t smem_u32(const void* p) {
    uint32_t a;
    asm("{ .reg .u64 t; cvta.to.shared.u64 t, %1; cvt.u32.u64 %0, t; }" : "=r"(a) : "l"(p));
    return a;
}
#define CP_ASYNC16(dst, src) \
    asm volatile("cp.async.cg.shared.global [%0], [%1], 16;" :: "r"(dst), "l"(src))
#define CP_COMMIT() asm volatile("cp.async.commit_group;" ::: "memory")
#define CP_WAIT(n)  asm volatile("cp.async.wait_group %0;" :: "n"(n) : "memory")
#define LDSM_X4(r0, r1, r2, r3, addr)                                        \
    asm volatile("ldmatrix.sync.aligned.m8n8.x4.shared.b16 {%0,%1,%2,%3}, [%4];" \
                 : "=r"(r0), "=r"(r1), "=r"(r2), "=r"(r3) : "r"(addr))
#define MMA_BF16(c, a, b)                                                    \
    asm volatile("mma.sync.aligned.m16n8k16.row.col.f32.bf16.bf16.f32 "      \
                 "{%0,%1,%2,%3},{%4,%5,%6,%7},{%8,%9},{%0,%1,%2,%3};"        \
                 : "+f"((c)[0]), "+f"((c)[1]), "+f"((c)[2]), "+f"((c)[3])    \
                 : "r"((a)[0]), "r"((a)[1]), "r"((a)[2]), "r"((a)[3]),       \
                   "r"((b)[0]), "r"((b)[1]))
__device__ __forceinline__ unsigned ld_acq(const unsigned* p) {
    unsigned v;
    asm volatile("ld.acquire.gpu.global.b32 %0, [%1];" : "=r"(v) : "l"(p) : "memory");
    return v;
}
__device__ __forceinline__ void st_rel(unsigned* p, unsigned v) {
    asm volatile("st.release.gpu.global.b32 [%0], %1;" :: "l"(p), "r"(v) : "memory");
}

// ---------------------------------------------------------------------------
// Split fp32 -> (hi, lo) bf16 pair
// ---------------------------------------------------------------------------
__global__ void split_bf16(const float* __restrict__ src, __nv_bfloat16* __restrict__ hi,
                           __nv_bfloat16* __restrict__ lo, int n) {
    int i = blockIdx.x * blockDim.x + threadIdx.x;
    if (i < n) {
        float v = src[i];
        __nv_bfloat16 h = __float2bfloat16(v);
        hi[i] = h;
        lo[i] = __float2bfloat16(v - __bfloat162float(h));
    }
}

// ---------------------------------------------------------------------------
// HMMA split-bf16 GEMM: g_xp[M=32768, N=2048] = A @ B^T + bias  (unchanged, proven)
// ---------------------------------------------------------------------------
#define XSTG 40960
#define TROW 80

__device__ __forceinline__ void xp_load_stage(uint32_t smb, int stage, int kc,
                                              int my, int nx, int tid) {
    const uint32_t sb = smb + stage * XSTG;
#pragma unroll
    for (int t = 0; t < 8; t++) {
        int i = tid + t * 256;
        int tile = i >> 9;
        int idx  = i & 511;
        int row  = idx >> 2;
        int q    = idx & 3;
        const __nv_bfloat16* src;
        int grow;
        if (tile == 0)      { src = g_Ahi; grow = my * 128 + row; }
        else if (tile == 1) { src = g_Alo; grow = my * 128 + row; }
        else if (tile == 2) { src = g_Bhi; grow = nx * 128 + row; }
        else                { src = g_Blo; grow = nx * 128 + row; }
        uint32_t dst = sb + tile * 10240 + row * TROW + q * 16;
        CP_ASYNC16(dst, src + (size_t)grow * IDIM + kc * 32 + q * 8);
    }
}

__global__ __launch_bounds__(256, 1)
void xproj_hmma(const float* __restrict__ bih, const float* __restrict__ bhh) {
    extern __shared__ char sm[];
    const uint32_t smb = smem_u32(sm);
    const int tid  = threadIdx.x;
    const int lane = tid & 31;
    const int wid  = tid >> 5;
    const int nx = blockIdx.x, my = blockIdx.y;
    const int warp_m = wid & 3, warp_n = wid >> 2;
    const int m_base = warp_m * 32, n_base = warp_n * 64;
    float* b_sh = (float*)(sm + 81920);

    if (tid < 128) b_sh[tid] = bih[nx * 128 + tid] + bhh[nx * 128 + tid];

    const uint32_t a_off = (uint32_t)(m_base + (lane & 15)) * TROW + (lane >> 4) * 16;
    const uint32_t b_off = (uint32_t)(n_base + (lane & 7) + ((lane >> 4) & 1) * 8) * TROW
                         + ((lane >> 3) & 1) * 16;

    float acc[2][8][4];
#pragma unroll
    for (int am = 0; am < 2; am++)
#pragma unroll
        for (int an = 0; an < 8; an++)
#pragma unroll
            for (int j = 0; j < 4; j++) acc[am][an][j] = 0.f;

    xp_load_stage(smb, 0, 0, my, nx, tid);
    CP_COMMIT();

    for (int c = 0; c < 16; c++) {
        if (c + 1 < 16) {
            xp_load_stage(smb, (c + 1) & 1, c + 1, my, nx, tid);
            CP_COMMIT();
            CP_WAIT(1);
        } else {
            CP_WAIT(0);
        }
        __syncthreads();

        const uint32_t sb = smb + (c & 1) * XSTG;
        const uint32_t aHi = sb + a_off;
        const uint32_t aLo = aHi + 10240;
        const uint32_t bHi = sb + 20480 + b_off;
        const uint32_t bLo = bHi + 10240;
#pragma unroll
        for (int ks = 0; ks < 2; ks++) {
            uint32_t ah[2][4], al[2][4], bh[8][2], bl[8][2];
            LDSM_X4(ah[0][0], ah[0][1], ah[0][2], ah[0][3], aHi + ks * 32);
            LDSM_X4(ah[1][0], ah[1][1], ah[1][2], ah[1][3], aHi + 1280 + ks * 32);
            LDSM_X4(al[0][0], al[0][1], al[0][2], al[0][3], aLo + ks * 32);
            LDSM_X4(al[1][0], al[1][1], al[1][2], al[1][3], aLo + 1280 + ks * 32);
#pragma unroll
            for (int p = 0; p < 4; p++) {
                LDSM_X4(bh[2*p][0], bh[2*p][1], bh[2*p+1][0], bh[2*p+1][1],
                        bHi + p * 1280 + ks * 32);
                LDSM_X4(bl[2*p][0], bl[2*p][1], bl[2*p+1][0], bl[2*p+1][1],
                        bLo + p * 1280 + ks * 32);
            }
#pragma unroll
            for (int am = 0; am < 2; am++)
#pragma unroll
                for (int an = 0; an < 8; an++) {
                    MMA_BF16(acc[am][an], ah[am], bh[an]);
                    MMA_BF16(acc[am][an], ah[am], bl[an]);
                    MMA_BF16(acc[am][an], al[am], bh[an]);
                }
        }
        __syncthreads();
    }

    const int qr = lane >> 2, qc = (lane & 3) * 2;
#pragma unroll
    for (int am = 0; am < 2; am++) {
        const size_t r0 = (size_t)my * 128 + m_base + am * 16 + qr;
#pragma unroll
        for (int an = 0; an < 8; an++) {
            const int cb = n_base + an * 8 + qc;
            const float b0 = b_sh[cb], b1 = b_sh[cb + 1];
            const size_t col = (size_t)nx * 128 + cb;
            *(float2*)&g_xp[r0 * G4H + col] =
                make_float2(acc[am][an][0] + b0, acc[am][an][1] + b1);
            *(float2*)&g_xp[(r0 + 8) * G4H + col] =
                make_float2(acc[am][an][2] + b0, acc[am][an][3] + b1);
        }
    }
}

// ---------------------------------------------------------------------------
// Atomic grid barrier — used ONCE at init (also resets flag state per replay)
// ---------------------------------------------------------------------------
__device__ __forceinline__ void grid_barrier() {
    __threadfence();
    __syncthreads();
    if (threadIdx.x == 0) {
        volatile unsigned* vgen = &g_gen;
        unsigned gen = *vgen;
        if (atomicAdd(&g_count, 1u) == NBLOCKS - 1u) {
            g_count = 0u;
            __threadfence();
            atomicAdd(&g_gen, 1u);
        } else {
            while (*vgen == gen) { __nanosleep(64); }
        }
    }
    __syncthreads();
}

// ---------------------------------------------------------------------------
// Persistent recurrence, tensor-core edition v2.
// 128 blocks = 64 col-groups (8 cols) x 2 batch-groups (32 batches).
// Per step per block: gates[32b, 32r] = h[32b,512] @ Whh_sub[32r,512]^T via
// split-bf16 HMMA. Warp decomposition: 8 K-eighths (K=64/warp); EACH warp
// computes the full 32x32 tile = 2m x 4n = 8 independent accumulators
// (12-deep MMA chains, interleavable) -> issue-bound, not latency-bound.
// SMEM (bytes): h_hi[0,33280) h_lo[33280,66560) w_hi[66560,99840)
//               w_lo[99840,133120) part[133120,169984)  (part pitch 36 floats)
// Sync: per-block release-flag array; batch-group independence; NO threadfence
// (syncthreads + st.release.gpu provides the release edge).
// ---------------------------------------------------------------------------
#define COLS 8
#define BB   32
#define HROWB 1040

__global__ __launch_bounds__(256, 1)
void lstm_rec(const float* __restrict__ Whh, float* __restrict__ out) {
    extern __shared__ char sm[];
    const uint32_t smb = smem_u32(sm);
    __nv_bfloat16* w_hi = (__nv_bfloat16*)(sm + 66560);
    __nv_bfloat16* w_lo = (__nv_bfloat16*)(sm + 99840);
    float* part = (float*)(sm + 133120);     // [8][32][36]

    const int tid  = threadIdx.x;
    const int lane = tid & 31;
    const int wid  = tid >> 5;
    const int colbase = blockIdx.x * COLS;
    const int bbase   = blockIdx.y * BB;
    const int fb      = (blockIdx.y << 6) + blockIdx.x;   // flag index

    // ---- init: split W_hh slice into SMEM (r = gate*8 + col, k-major) ----
    for (int idx = tid; idx < 32 * 512; idx += 256) {
        int r = idx >> 9, k = idx & 511;
        int g = r >> 3, c = r & 7;
        float v = __ldg(&Whh[((size_t)(g * HDIM + colbase + c)) * HDIM + k]);
        __nv_bfloat16 h = __float2bfloat16(v);
        w_hi[r * 520 + k] = h;
        w_lo[r * 520 + k] = __float2bfloat16(v - __bfloat162float(h));
    }
    {
        int b = tid >> 3, c = tid & 7;
        g_hh[0][(bbase + b) * HDIM + colbase + c] = __float2bfloat16(0.f);
        g_hl[0][(bbase + b) * HDIM + colbase + c] = __float2bfloat16(0.f);
    }
    if (tid == 0) g_flags[fb] = 0u;
    grid_barrier();

    // warp = K-eighth; computes full 32x32 tile (2 m16 x 4 n8 atoms)
    const int kh = wid;                          // 0..7, K range [kh*64, kh*64+64)
    const uint32_t a_off = (uint32_t)(lane & 15) * HROWB
                         + (lane >> 4) * 16 + kh * 128;
    const uint32_t b_off = (uint32_t)((lane & 7) + ((lane >> 4) & 1) * 8) * HROWB
                         + ((lane >> 3) & 1) * 16 + kh * 128;
    const uint32_t aHi = smb + a_off;
    const uint32_t aLo = aHi + 33280;
    const uint32_t bHi = smb + 66560 + b_off;
    const uint32_t bLo = bHi + 33280;

    const int qr = lane >> 2, qc = (lane & 3) * 2;
    const int b_ep = tid >> 3;         // epilogue batch 0..31
    const int c_ep = tid & 7;          // epilogue col 0..7
    float creg = 0.f;

    for (int t = 0; t < T_STEPS; t++) {
        const int cur = t & 1;
        // prefetch x_proj gates (issues before the poll; DRAM latency overlaps)
        float xp[4];
        {
            const float* xpp = g_xp + ((size_t)t * NBATCH + (bbase + b_ep)) * G4H
                               + colbase + c_ep;
#pragma unroll
            for (int g = 0; g < 4; g++) xp[g] = __ldg(xpp + (size_t)g * HDIM);
        }
        // wait for our batch-group's producers to finish step t-1
        if (t > 0 && tid < 64) {
            const unsigned* fp = &g_flags[(blockIdx.y << 6) + tid];
            while (ld_acq(fp) < (unsigned)t) { }
        }
        __syncthreads();

        // stage h slice (32 batches x 512, hi+lo) into SMEM via cp.async
        {
            const __nv_bfloat16* shi = g_hh[cur] + (size_t)bbase * HDIM;
            const __nv_bfloat16* slo = g_hl[cur] + (size_t)bbase * HDIM;
#pragma unroll
            for (int it = 0; it < 16; it++) {
                int i = tid + it * 256;          // 0..4095
                int half = i >> 11;
                int idx  = i & 2047;
                int b    = idx >> 6;
                int k8   = idx & 63;
                const __nv_bfloat16* src = (half ? slo : shi) + (size_t)b * HDIM + k8 * 8;
                CP_ASYNC16(smb + half * 33280 + b * HROWB + k8 * 16, src);
            }
        }
        CP_COMMIT();
        CP_WAIT(0);
        __syncthreads();

        // micro-GEMM: full 32x32 over this warp's K-eighth (4 k16 steps)
        float acc[2][4][4];
#pragma unroll
        for (int am = 0; am < 2; am++)
#pragma unroll
            for (int an = 0; an < 4; an++)
#pragma unroll
                for (int j = 0; j < 4; j++) acc[am][an][j] = 0.f;

#pragma unroll
        for (int ks = 0; ks < 4; ks++) {
            uint32_t ah[2][4], al[2][4], bh[4][2], bl[4][2];
            LDSM_X4(ah[0][0], ah[0][1], ah[0][2], ah[0][3], aHi + ks * 32);
            LDSM_X4(ah[1][0], ah[1][1], ah[1][2], ah[1][3], aHi + 16 * HROWB + ks * 32);
            LDSM_X4(al[0][0], al[0][1], al[0][2], al[0][3], aLo + ks * 32);
            LDSM_X4(al[1][0], al[1][1], al[1][2], al[1][3], aLo + 16 * HROWB + ks * 32);
#pragma unroll
            for (int p = 0; p < 2; p++) {
                LDSM_X4(bh[2*p][0], bh[2*p][1], bh[2*p+1][0], bh[2*p+1][1],
                        bHi + p * 16 * HROWB + ks * 32);
                LDSM_X4(bl[2*p][0], bl[2*p][1], bl[2*p+1][0], bl[2*p+1][1],
                        bLo + p * 16 * HROWB + ks * 32);
            }
#pragma unroll
            for (int am = 0; am < 2; am++)
#pragma unroll
                for (int an = 0; an < 4; an++) {
                    MMA_BF16(acc[am][an], ah[am], bh[an]);
                    MMA_BF16(acc[am][an], ah[am], bl[an]);
                    MMA_BF16(acc[am][an], al[am], bh[an]);
                }
        }
        // store K-eighth partials (pitch 36 floats; (4b+c) distinct mod 32)
        {
            float* pp = part + kh * 1152;
#pragma unroll
            for (int am = 0; am < 2; am++) {
                const int row0 = am * 16 + qr;
#pragma unroll
                for (int an = 0; an < 4; an++) {
                    const int col = an * 8 + qc;
                    *(float2*)&pp[row0 * 36 + col] = make_float2(acc[am][an][0], acc[am][an][1]);
                    *(float2*)&pp[(row0 + 8) * 36 + col] = make_float2(acc[am][an][2], acc[am][an][3]);
                }
            }
        }
        __syncthreads();

        // epilogue: one (batch,col) per thread; 8-way partial reduce
        {
            float s[4];
#pragma unroll
            for (int g = 0; g < 4; g++) {
                int r = g * 8 + c_ep;
                float v = 0.f;
#pragma unroll
                for (int kq = 0; kq < 8; kq++)
                    v += part[kq * 1152 + b_ep * 36 + r];
                s[g] = v + xp[g];
            }
            float iv = 1.f / (1.f + expf(-s[0]));
            float fv = 1.f / (1.f + expf(-s[1]));
            float gv = tanhf(s[2]);
            float ov = 1.f / (1.f + expf(-s[3]));
            creg = fv * creg + iv * gv;
            float hn = ov * tanhf(creg);
            __nv_bfloat16 hh = __float2bfloat16(hn);
            __nv_bfloat16 hl = __float2bfloat16(hn - __bfloat162float(hh));
            const size_t hidx = (size_t)(bbase + b_ep) * HDIM + colbase + c_ep;
            g_hh[cur ^ 1][hidx] = hh;
            g_hl[cur ^ 1][hidx] = hl;
            out[((size_t)t * NBATCH + bbase + b_ep) * HDIM + colbase + c_ep] = hn;
        }
        // release: syncthreads orders all threads' h stores before tid0's
        // release store (morally-strong chain; no extra fence needed)
        __syncthreads();
        if (tid == 0) st_rel(&g_flags[fb], (unsigned)(t + 1));
    }
}

// ---------------------------------------------------------------------------
extern "C" void kernel_launch(void* const* d_in, const int* in_sizes, int n_in,
                              void* d_out, int out_size) {
    const float* x   = (const float*)d_in[0];
    const float* Wih = (const float*)d_in[1];
    const float* Whh = (const float*)d_in[2];
    const float* bih = (const float*)d_in[3];
    const float* bhh = (const float*)d_in[4];
    float* out = (float*)d_out;

    cudaFuncSetAttribute((const void*)xproj_hmma,
                         cudaFuncAttributeMaxDynamicSharedMemorySize, 82944);
    cudaFuncSetAttribute((const void*)lstm_rec,
                         cudaFuncAttributeMaxDynamicSharedMemorySize, 169984);

    __nv_bfloat16 *ahi, *alo, *bhi, *blo;
    cudaGetSymbolAddress((void**)&ahi, g_Ahi);
    cudaGetSymbolAddress((void**)&alo, g_Alo);
    cudaGetSymbolAddress((void**)&bhi, g_Bhi);
    cudaGetSymbolAddress((void**)&blo, g_Blo);

    const int nA = T_STEPS * NBATCH * IDIM;   // 16.8M
    const int nB = G4H * IDIM;                // 1M
    split_bf16<<<(nA + 255) / 256, 256>>>(x, ahi, alo, nA);
    split_bf16<<<(nB + 255) / 256, 256>>>(Wih, bhi, blo, nB);

    xproj_hmma<<<dim3(G4H / 128, (T_STEPS * NBATCH) / 128), 256, 82944>>>(bih, bhh);
    lstm_rec<<<dim3(64, 2), 256, 169984>>>(Whh, out);
}

// round 16
// speedup vs baseline: 1.2627x; 1.0361x over previous
#include <cuda_runtime.h>
#include <cuda_bf16.h>
#include <cstdint>

#define T_STEPS 512
#define NBATCH  64
#define IDIM    512
#define HDIM    512
#define G4H     2048
#define NBLOCKS 128

// ---------------- device scratch (allocation-free rule) ----------------
__device__ float         g_xp[(size_t)T_STEPS * NBATCH * G4H];  // [T*B, 4H]
__device__ __nv_bfloat16 g_hh[2][NBATCH * HDIM];                // ping-pong h hi [b][k]
__device__ __nv_bfloat16 g_hl[2][NBATCH * HDIM];                // ping-pong h lo [b][k]
__device__ unsigned      g_flags[NBLOCKS];                      // per-block step counters
__device__ unsigned      g_count;
__device__ unsigned      g_gen;
__device__ __nv_bfloat16 g_Ahi[(size_t)T_STEPS * NBATCH * IDIM];
__device__ __nv_bfloat16 g_Alo[(size_t)T_STEPS * NBATCH * IDIM];
__device__ __nv_bfloat16 g_Bhi[(size_t)G4H * IDIM];
__device__ __nv_bfloat16 g_Blo[(size_t)G4H * IDIM];

// ---------------- portable PTX helpers (valid on plain sm_103) ----------------
__device__ __forceinline__ uint32_t smem_u32(const void* p) {
    uint32_t a;
    asm("{ .reg .u64 t; cvta.to.shared.u64 t, %1; cvt.u32.u64 %0, t; }" : "=r"(a) : "l"(p));
    return a;
}
#define CP_ASYNC16(dst, src) \
    asm volatile("cp.async.cg.shared.global [%0], [%1], 16;" :: "r"(dst), "l"(src))
#define CP_COMMIT() asm volatile("cp.async.commit_group;" ::: "memory")
#define CP_WAIT(n)  asm volatile("cp.async.wait_group %0;" :: "n"(n) : "memory")
#define LDSM_X4(r0, r1, r2, r3, addr)                                        \
    asm volatile("ldmatrix.sync.aligned.m8n8.x4.shared.b16 {%0,%1,%2,%3}, [%4];" \
                 : "=r"(r0), "=r"(r1), "=r"(r2), "=r"(r3) : "r"(addr))
#define MMA_BF16(c, a, b)                                                    \
    asm volatile("mma.sync.aligned.m16n8k16.row.col.f32.bf16.bf16.f32 "      \
                 "{%0,%1,%2,%3},{%4,%5,%6,%7},{%8,%9},{%0,%1,%2,%3};"        \
                 : "+f"((c)[0]), "+f"((c)[1]), "+f"((c)[2]), "+f"((c)[3])    \
                 : "r"((a)[0]), "r"((a)[1]), "r"((a)[2]), "r"((a)[3]),       \
                   "r"((b)[0]), "r"((b)[1]))
__device__ __forceinline__ unsigned ld_acq(const unsigned* p) {
    unsigned v;
    asm volatile("ld.acquire.gpu.global.b32 %0, [%1];" : "=r"(v) : "l"(p) : "memory");
    return v;
}
__device__ __forceinline__ void st_rel(unsigned* p, unsigned v) {
    asm volatile("st.release.gpu.global.b32 [%0], %1;" :: "l"(p), "r"(v) : "memory");
}

// ---------------------------------------------------------------------------
// Split fp32 -> (hi, lo) bf16 pair
// ---------------------------------------------------------------------------
__global__ void split_bf16(const float* __restrict__ src, __nv_bfloat16* __restrict__ hi,
                           __nv_bfloat16* __restrict__ lo, int n) {
    int i = blockIdx.x * blockDim.x + threadIdx.x;
    if (i < n) {
        float v = src[i];
        __nv_bfloat16 h = __float2bfloat16(v);
        hi[i] = h;
        lo[i] = __float2bfloat16(v - __bfloat162float(h));
    }
}

// ---------------------------------------------------------------------------
// HMMA split-bf16 GEMM: g_xp[M=32768, N=2048] = A @ B^T + bias  (unchanged, proven)
// ---------------------------------------------------------------------------
#define XSTG 40960
#define TROW 80

__device__ __forceinline__ void xp_load_stage(uint32_t smb, int stage, int kc,
                                              int my, int nx, int tid) {
    const uint32_t sb = smb + stage * XSTG;
#pragma unroll
    for (int t = 0; t < 8; t++) {
        int i = tid + t * 256;
        int tile = i >> 9;
        int idx  = i & 511;
        int row  = idx >> 2;
        int q    = idx & 3;
        const __nv_bfloat16* src;
        int grow;
        if (tile == 0)      { src = g_Ahi; grow = my * 128 + row; }
        else if (tile == 1) { src = g_Alo; grow = my * 128 + row; }
        else if (tile == 2) { src = g_Bhi; grow = nx * 128 + row; }
        else                { src = g_Blo; grow = nx * 128 + row; }
        uint32_t dst = sb + tile * 10240 + row * TROW + q * 16;
        CP_ASYNC16(dst, src + (size_t)grow * IDIM + kc * 32 + q * 8);
    }
}

__global__ __launch_bounds__(256, 1)
void xproj_hmma(const float* __restrict__ bih, const float* __restrict__ bhh) {
    extern __shared__ char sm[];
    const uint32_t smb = smem_u32(sm);
    const int tid  = threadIdx.x;
    const int lane = tid & 31;
    const int wid  = tid >> 5;
    const int nx = blockIdx.x, my = blockIdx.y;
    const int warp_m = wid & 3, warp_n = wid >> 2;
    const int m_base = warp_m * 32, n_base = warp_n * 64;
    float* b_sh = (float*)(sm + 81920);

    if (tid < 128) b_sh[tid] = bih[nx * 128 + tid] + bhh[nx * 128 + tid];

    const uint32_t a_off = (uint32_t)(m_base + (lane & 15)) * TROW + (lane >> 4) * 16;
    const uint32_t b_off = (uint32_t)(n_base + (lane & 7) + ((lane >> 4) & 1) * 8) * TROW
                         + ((lane >> 3) & 1) * 16;

    float acc[2][8][4];
#pragma unroll
    for (int am = 0; am < 2; am++)
#pragma unroll
        for (int an = 0; an < 8; an++)
#pragma unroll
            for (int j = 0; j < 4; j++) acc[am][an][j] = 0.f;

    xp_load_stage(smb, 0, 0, my, nx, tid);
    CP_COMMIT();

    for (int c = 0; c < 16; c++) {
        if (c + 1 < 16) {
            xp_load_stage(smb, (c + 1) & 1, c + 1, my, nx, tid);
            CP_COMMIT();
            CP_WAIT(1);
        } else {
            CP_WAIT(0);
        }
        __syncthreads();

        const uint32_t sb = smb + (c & 1) * XSTG;
        const uint32_t aHi = sb + a_off;
        const uint32_t aLo = aHi + 10240;
        const uint32_t bHi = sb + 20480 + b_off;
        const uint32_t bLo = bHi + 10240;
#pragma unroll
        for (int ks = 0; ks < 2; ks++) {
            uint32_t ah[2][4], al[2][4], bh[8][2], bl[8][2];
            LDSM_X4(ah[0][0], ah[0][1], ah[0][2], ah[0][3], aHi + ks * 32);
            LDSM_X4(ah[1][0], ah[1][1], ah[1][2], ah[1][3], aHi + 1280 + ks * 32);
            LDSM_X4(al[0][0], al[0][1], al[0][2], al[0][3], aLo + ks * 32);
            LDSM_X4(al[1][0], al[1][1], al[1][2], al[1][3], aLo + 1280 + ks * 32);
#pragma unroll
            for (int p = 0; p < 4; p++) {
                LDSM_X4(bh[2*p][0], bh[2*p][1], bh[2*p+1][0], bh[2*p+1][1],
                        bHi + p * 1280 + ks * 32);
                LDSM_X4(bl[2*p][0], bl[2*p][1], bl[2*p+1][0], bl[2*p+1][1],
                        bLo + p * 1280 + ks * 32);
            }
#pragma unroll
            for (int am = 0; am < 2; am++)
#pragma unroll
                for (int an = 0; an < 8; an++) {
                    MMA_BF16(acc[am][an], ah[am], bh[an]);
                    MMA_BF16(acc[am][an], ah[am], bl[an]);
                    MMA_BF16(acc[am][an], al[am], bh[an]);
                }
        }
        __syncthreads();
    }

    const int qr = lane >> 2, qc = (lane & 3) * 2;
#pragma unroll
    for (int am = 0; am < 2; am++) {
        const size_t r0 = (size_t)my * 128 + m_base + am * 16 + qr;
#pragma unroll
        for (int an = 0; an < 8; an++) {
            const int cb = n_base + an * 8 + qc;
            const float b0 = b_sh[cb], b1 = b_sh[cb + 1];
            const size_t col = (size_t)nx * 128 + cb;
            *(float2*)&g_xp[r0 * G4H + col] =
                make_float2(acc[am][an][0] + b0, acc[am][an][1] + b1);
            *(float2*)&g_xp[(r0 + 8) * G4H + col] =
                make_float2(acc[am][an][2] + b0, acc[am][an][3] + b1);
        }
    }
}

// ---------------------------------------------------------------------------
// Atomic grid barrier — used ONCE at init (also resets flag state per replay)
// ---------------------------------------------------------------------------
__device__ __forceinline__ void grid_barrier() {
    __threadfence();
    __syncthreads();
    if (threadIdx.x == 0) {
        volatile unsigned* vgen = &g_gen;
        unsigned gen = *vgen;
        if (atomicAdd(&g_count, 1u) == NBLOCKS - 1u) {
            g_count = 0u;
            __threadfence();
            atomicAdd(&g_gen, 1u);
        } else {
            while (*vgen == gen) { __nanosleep(64); }
        }
    }
    __syncthreads();
}

// ---------------------------------------------------------------------------
// Persistent recurrence, tensor-core edition v3 (warp-autonomous pipeline).
// 128 blocks = 64 col-groups (8 cols) x 2 batch-groups (32 batches).
// Warp kh owns K-eighth [kh*64, kh*64+64):
//   - polls ONLY its 8 producer blocks' flags (lanes 0-7)
//   - stages ONLY its 8KB h-slice (private cp.async group, no block sync)
//   - computes the full 32x32 tile over its K-eighth (8 indep accumulators)
// Block-wide syncs only around the partial-reduce epilogue (2 per step).
// The post-partials __syncthreads orders the epilogue after ALL warps' polls
// (union of 8x8 flags = all 64 group flags >= t), preserving the ping-pong
// overwrite-safety argument of the full barrier.
// SMEM (bytes): h_hi[0,33280) h_lo[33280,66560) w_hi[66560,99840)
//               w_lo[99840,133120) part[133120,169984)  (part pitch 36 floats)
// ---------------------------------------------------------------------------
#define COLS 8
#define BB   32
#define HROWB 1040

__global__ __launch_bounds__(256, 1)
void lstm_rec(const float* __restrict__ Whh, float* __restrict__ out) {
    extern __shared__ char sm[];
    const uint32_t smb = smem_u32(sm);
    __nv_bfloat16* w_hi = (__nv_bfloat16*)(sm + 66560);
    __nv_bfloat16* w_lo = (__nv_bfloat16*)(sm + 99840);
    float* part = (float*)(sm + 133120);     // [8][32][36]

    const int tid  = threadIdx.x;
    const int lane = tid & 31;
    const int wid  = tid >> 5;
    const int colbase = blockIdx.x * COLS;
    const int bbase   = blockIdx.y * BB;
    const int fb      = (blockIdx.y << 6) + blockIdx.x;   // flag index

    // ---- init: split W_hh slice into SMEM (r = gate*8 + col, k-major) ----
    for (int idx = tid; idx < 32 * 512; idx += 256) {
        int r = idx >> 9, k = idx & 511;
        int g = r >> 3, c = r & 7;
        float v = __ldg(&Whh[((size_t)(g * HDIM + colbase + c)) * HDIM + k]);
        __nv_bfloat16 h = __float2bfloat16(v);
        w_hi[r * 520 + k] = h;
        w_lo[r * 520 + k] = __float2bfloat16(v - __bfloat162float(h));
    }
    {
        int b = tid >> 3, c = tid & 7;
        g_hh[0][(bbase + b) * HDIM + colbase + c] = __float2bfloat16(0.f);
        g_hl[0][(bbase + b) * HDIM + colbase + c] = __float2bfloat16(0.f);
    }
    if (tid == 0) g_flags[fb] = 0u;
    grid_barrier();

    // warp = K-eighth; computes full 32x32 tile (2 m16 x 4 n8 atoms)
    const int kh = wid;                          // 0..7, K range [kh*64, kh*64+64)
    const uint32_t a_off = (uint32_t)(lane & 15) * HROWB
                         + (lane >> 4) * 16 + kh * 128;
    const uint32_t b_off = (uint32_t)((lane & 7) + ((lane >> 4) & 1) * 8) * HROWB
                         + ((lane >> 3) & 1) * 16 + kh * 128;
    const uint32_t aHi = smb + a_off;
    const uint32_t aLo = aHi + 33280;
    const uint32_t bHi = smb + 66560 + b_off;
    const uint32_t bLo = bHi + 33280;

    const int qr = lane >> 2, qc = (lane & 3) * 2;
    const int b_ep = tid >> 3;         // epilogue batch 0..31
    const int c_ep = tid & 7;          // epilogue col 0..7
    // this warp's 8 producer flags (cols kh*64 .. kh*64+63 = blocks kh*8..+7)
    const unsigned* my_flag = &g_flags[(blockIdx.y << 6) + (kh << 3) + (lane & 7)];
    float creg = 0.f;

    for (int t = 0; t < T_STEPS; t++) {
        const int cur = t & 1;
        // prefetch x_proj gates (issues before the poll; DRAM latency overlaps)
        float xp[4];
        {
            const float* xpp = g_xp + ((size_t)t * NBATCH + (bbase + b_ep)) * G4H
                               + colbase + c_ep;
#pragma unroll
            for (int g = 0; g < 4; g++) xp[g] = __ldg(xpp + (size_t)g * HDIM);
        }
        // warp-private wait: only OUR 8 producer blocks must have finished t-1
        if (t > 0) {
            if (lane < 8) {
                while (ld_acq(my_flag) < (unsigned)t) { }
            }
            __syncwarp();
        }

        // warp-private h-slice staging: 32 batches x 64 k, hi+lo = 8KB
        {
            const __nv_bfloat16* shi = g_hh[cur] + (size_t)bbase * HDIM + kh * 64;
            const __nv_bfloat16* slo = g_hl[cur] + (size_t)bbase * HDIM + kh * 64;
#pragma unroll
            for (int it = 0; it < 16; it++) {
                int i = lane + it * 32;          // 0..511
                int half = i >> 8;               // 0 hi, 1 lo
                int idx  = i & 255;              // b*8 + k8
                int b    = idx >> 3;
                int k8   = idx & 7;
                const __nv_bfloat16* src = (half ? slo : shi) + (size_t)b * HDIM + k8 * 8;
                CP_ASYNC16(smb + half * 33280 + b * HROWB + kh * 128 + k8 * 16, src);
            }
        }
        CP_COMMIT();
        CP_WAIT(0);
        __syncwarp();

        // micro-GEMM: full 32x32 over this warp's K-eighth (4 k16 steps)
        float acc[2][4][4];
#pragma unroll
        for (int am = 0; am < 2; am++)
#pragma unroll
            for (int an = 0; an < 4; an++)
#pragma unroll
                for (int j = 0; j < 4; j++) acc[am][an][j] = 0.f;

#pragma unroll
        for (int ks = 0; ks < 4; ks++) {
            uint32_t ah[2][4], al[2][4], bh[4][2], bl[4][2];
            LDSM_X4(ah[0][0], ah[0][1], ah[0][2], ah[0][3], aHi + ks * 32);
            LDSM_X4(ah[1][0], ah[1][1], ah[1][2], ah[1][3], aHi + 16 * HROWB + ks * 32);
            LDSM_X4(al[0][0], al[0][1], al[0][2], al[0][3], aLo + ks * 32);
            LDSM_X4(al[1][0], al[1][1], al[1][2], al[1][3], aLo + 16 * HROWB + ks * 32);
#pragma unroll
            for (int p = 0; p < 2; p++) {
                LDSM_X4(bh[2*p][0], bh[2*p][1], bh[2*p+1][0], bh[2*p+1][1],
                        bHi + p * 16 * HROWB + ks * 32);
                LDSM_X4(bl[2*p][0], bl[2*p][1], bl[2*p+1][0], bl[2*p+1][1],
                        bLo + p * 16 * HROWB + ks * 32);
            }
#pragma unroll
            for (int am = 0; am < 2; am++)
#pragma unroll
                for (int an = 0; an < 4; an++) {
                    MMA_BF16(acc[am][an], ah[am], bh[an]);
                    MMA_BF16(acc[am][an], ah[am], bl[an]);
                    MMA_BF16(acc[am][an], al[am], bh[an]);
                }
        }
        // store K-eighth partials (pitch 36 floats)
        {
            float* pp = part + kh * 1152;
#pragma unroll
            for (int am = 0; am < 2; am++) {
                const int row0 = am * 16 + qr;
#pragma unroll
                for (int an = 0; an < 4; an++) {
                    const int col = an * 8 + qc;
                    *(float2*)&pp[row0 * 36 + col] = make_float2(acc[am][an][0], acc[am][an][1]);
                    *(float2*)&pp[(row0 + 8) * 36 + col] = make_float2(acc[am][an][2], acc[am][an][3]);
                }
            }
        }
        __syncthreads();   // partials ready; also orders epilogue after ALL polls

        // epilogue: one (batch,col) per thread; 8-way partial reduce
        {
            float s[4];
#pragma unroll
            for (int g = 0; g < 4; g++) {
                int r = g * 8 + c_ep;
                float v = 0.f;
#pragma unroll
                for (int kq = 0; kq < 8; kq++)
                    v += part[kq * 1152 + b_ep * 36 + r];
                s[g] = v + xp[g];
            }
            float iv = 1.f / (1.f + expf(-s[0]));
            float fv = 1.f / (1.f + expf(-s[1]));
            float gv = tanhf(s[2]);
            float ov = 1.f / (1.f + expf(-s[3]));
            creg = fv * creg + iv * gv;
            float hn = ov * tanhf(creg);
            __nv_bfloat16 hh = __float2bfloat16(hn);
            __nv_bfloat16 hl = __float2bfloat16(hn - __bfloat162float(hh));
            const size_t hidx = (size_t)(bbase + b_ep) * HDIM + colbase + c_ep;
            g_hh[cur ^ 1][hidx] = hh;
            g_hl[cur ^ 1][hidx] = hl;
            out[((size_t)t * NBATCH + bbase + b_ep) * HDIM + colbase + c_ep] = hn;
        }
        // release: syncthreads orders all threads' h stores before tid0's
        // release store (morally-strong chain)
        __syncthreads();
        if (tid == 0) st_rel(&g_flags[fb], (unsigned)(t + 1));
    }
}

// ---------------------------------------------------------------------------
extern "C" void kernel_launch(void* const* d_in, const int* in_sizes, int n_in,
                              void* d_out, int out_size) {
    const float* x   = (const float*)d_in[0];
    const float* Wih = (const float*)d_in[1];
    const float* Whh = (const float*)d_in[2];
    const float* bih = (const float*)d_in[3];
    const float* bhh = (const float*)d_in[4];
    float* out = (float*)d_out;

    cudaFuncSetAttribute((const void*)xproj_hmma,
                         cudaFuncAttributeMaxDynamicSharedMemorySize, 82944);
    cudaFuncSetAttribute((const void*)lstm_rec,
                         cudaFuncAttributeMaxDynamicSharedMemorySize, 169984);

    __nv_bfloat16 *ahi, *alo, *bhi, *blo;
    cudaGetSymbolAddress((void**)&ahi, g_Ahi);
    cudaGetSymbolAddress((void**)&alo, g_Alo);
    cudaGetSymbolAddress((void**)&bhi, g_Bhi);
    cudaGetSymbolAddress((void**)&blo, g_Blo);

    const int nA = T_STEPS * NBATCH * IDIM;   // 16.8M
    const int nB = G4H * IDIM;                // 1M
    split_bf16<<<(nA + 255) / 256, 256>>>(x, ahi, alo, nA);
    split_bf16<<<(nB + 255) / 256, 256>>>(Wih, bhi, blo, nB);

    xproj_hmma<<<dim3(G4H / 128, (T_STEPS * NBATCH) / 128), 256, 82944>>>(bih, bhh);
    lstm_rec<<<dim3(64, 2), 256, 169984>>>(Whh, out);
}